// round 2
// baseline (speedup 1.0000x reference)
#include <cuda_runtime.h>
#include <cstdint>

// Problem constants
#define BB    2
#define CIN   256
#define HH    56
#define WW    56
#define OUTC  256
#define KK    7
#define PADV  3
#define GRP   8
#define CG    32
#define HP    62
#define WP    62
#define NQ    (HH*WW)     // 3136
#define NP    (HP*WP)     // 3844

typedef unsigned long long u64;

// Packed fp32x2 FMA (FFMA2): 2 fp32 FMAs per instruction, fma pipe.
#define FMA_F32X2(d, a, b, c) \
    asm("fma.rn.f32x2 %0, %1, %2, %3;" : "=l"(d) : "l"(a), "l"(b), "l"(c))

__device__ __forceinline__ u64 d2u(double v) { return __double_as_longlong(v); }
__device__ __forceinline__ float2 unpk(u64 v) {
    float2 r;
    r.x = __int_as_float((int)(v & 0xffffffffu));
    r.y = __int_as_float((int)(v >> 32));
    return r;
}

// ---------------------------------------------------------------------------
// Scratch (device globals)
// ---------------------------------------------------------------------------
__device__ float g_pad[BB * CIN * NP];
__device__ float g_q  [BB * NQ  * OUTC];
__device__ float g_k  [BB * NP  * OUTC];
__device__ float g_v  [BB * NP  * OUTC];

// ---------------------------------------------------------------------------
// 1) Pad
// ---------------------------------------------------------------------------
__global__ void pad_kernel(const float* __restrict__ fm) {
    int idx = blockIdx.x * blockDim.x + threadIdx.x;
    const int total = BB * CIN * NP;
    if (idx >= total) return;
    int x = idx % WP;
    int t = idx / WP;
    int y = t % HP;  t /= HP;
    int c = t % CIN;
    int b = t / CIN;
    float v = 0.f;
    int hy = y - PADV, wx = x - PADV;
    if (hy >= 0 && hy < HH && wx >= 0 && wx < WW)
        v = fm[((size_t)(b * 2 * CIN + c) * HH + hy) * WW + wx];
    g_pad[idx] = v;
}

// ---------------------------------------------------------------------------
// 2) GEMM-Q with packed FFMA2.
//    As[k][m]: m pairs adjacent.  Bs[k][2n+d]: each B value DUPLICATED so a
//    64-bit load yields a broadcast pair.  Thread covers m = tx*8..tx*8+7,
//    n = ty*4..ty*4+3.
// ---------------------------------------------------------------------------
__global__ __launch_bounds__(256) void gemm_q(const float* __restrict__ fm,
                                              const float* __restrict__ wq) {
    __shared__ float As[16][128];
    __shared__ float Bs[16][132];           // 64 n-values duplicated (128) + pad
    const int b  = blockIdx.z;
    const int o0 = blockIdx.y * 128;
    const int n0 = blockIdx.x * 64;
    const float* inp = fm + (size_t)b * (2 * CIN) * NQ + (size_t)CIN * NQ; // fm_t1
    const int t  = threadIdx.x;
    const int tx = t & 15;
    const int ty = t >> 4;

    u64 acc[4][4];
#pragma unroll
    for (int i = 0; i < 4; i++)
#pragma unroll
        for (int j = 0; j < 4; j++) acc[i][j] = 0ull;

    for (int k0 = 0; k0 < CIN; k0 += 16) {
#pragma unroll
        for (int r = 0; r < 2; r++) {
            int q  = t + r * 256;
            int m  = q & 127;
            int k4 = q >> 7;
            float4 a = *(const float4*)&wq[(size_t)(o0 + m) * CIN + k0 + k4 * 4];
            As[k4 * 4 + 0][m] = a.x;
            As[k4 * 4 + 1][m] = a.y;
            As[k4 * 4 + 2][m] = a.z;
            As[k4 * 4 + 3][m] = a.w;
        }
        {
            int k  = t >> 4;
            int n4 = t & 15;
            float4 v = *(const float4*)&inp[(size_t)(k0 + k) * NQ + n0 + n4 * 4];
            float4 d0 = {v.x, v.x, v.y, v.y};
            float4 d1 = {v.z, v.z, v.w, v.w};
            *(float4*)&Bs[k][n4 * 8]     = d0;
            *(float4*)&Bs[k][n4 * 8 + 4] = d1;
        }
        __syncthreads();
#pragma unroll
        for (int k = 0; k < 16; k++) {
            double2 bA = *(const double2*)&Bs[k][ty * 8];      // dup(n0), dup(n1)
            double2 bB = *(const double2*)&Bs[k][ty * 8 + 4];  // dup(n2), dup(n3)
            double2 aA = *(const double2*)&As[k][tx * 8];      // (m0,m1),(m2,m3)
            double2 aB = *(const double2*)&As[k][tx * 8 + 4];  // (m4,m5),(m6,m7)
            u64 bn[4] = {d2u(bA.x), d2u(bA.y), d2u(bB.x), d2u(bB.y)};
            u64 am[4] = {d2u(aA.x), d2u(aA.y), d2u(aB.x), d2u(aB.y)};
#pragma unroll
            for (int i = 0; i < 4; i++)
#pragma unroll
                for (int j = 0; j < 4; j++)
                    FMA_F32X2(acc[i][j], bn[i], am[j], acc[i][j]);
        }
        __syncthreads();
    }
#pragma unroll
    for (int i = 0; i < 4; i++) {
        int n = n0 + ty * 4 + i;
        size_t base = ((size_t)b * NQ + n) * OUTC + o0 + tx * 8;
        float2 p0 = unpk(acc[i][0]), p1 = unpk(acc[i][1]);
        float2 p2 = unpk(acc[i][2]), p3 = unpk(acc[i][3]);
        float4 s0 = {p0.x, p0.y, p1.x, p1.y};
        float4 s1 = {p2.x, p2.y, p3.x, p3.y};
        *(float4*)&g_q[base]     = s0;
        *(float4*)&g_q[base + 4] = s1;
    }
}

// ---------------------------------------------------------------------------
// 3) Fused GEMM-KV with packed FFMA2 (shares the duplicated B tile)
// ---------------------------------------------------------------------------
__global__ __launch_bounds__(256) void gemm_kv(const float* __restrict__ wk,
                                               const float* __restrict__ wv) {
    __shared__ float Ak[16][128];
    __shared__ float Av[16][128];
    __shared__ float Bs[16][132];
    const int b  = blockIdx.z;
    const int o0 = blockIdx.y * 128;
    const int n0 = blockIdx.x * 64;
    const float* inp = g_pad + (size_t)b * CIN * NP;
    const int t  = threadIdx.x;
    const int tx = t & 15;
    const int ty = t >> 4;

    u64 ck[4][4], cv[4][4];
#pragma unroll
    for (int i = 0; i < 4; i++)
#pragma unroll
        for (int j = 0; j < 4; j++) { ck[i][j] = 0ull; cv[i][j] = 0ull; }

    for (int k0 = 0; k0 < CIN; k0 += 16) {
#pragma unroll
        for (int r = 0; r < 2; r++) {
            int q  = t + r * 256;
            int m  = q & 127;
            int k4 = q >> 7;
            float4 a = *(const float4*)&wk[(size_t)(o0 + m) * CIN + k0 + k4 * 4];
            Ak[k4 * 4 + 0][m] = a.x;
            Ak[k4 * 4 + 1][m] = a.y;
            Ak[k4 * 4 + 2][m] = a.z;
            Ak[k4 * 4 + 3][m] = a.w;
            float4 c = *(const float4*)&wv[(size_t)(o0 + m) * CIN + k0 + k4 * 4];
            Av[k4 * 4 + 0][m] = c.x;
            Av[k4 * 4 + 1][m] = c.y;
            Av[k4 * 4 + 2][m] = c.z;
            Av[k4 * 4 + 3][m] = c.w;
        }
        {
            int k  = t >> 4;
            int n4 = t & 15;
            int n  = n0 + n4 * 4;
            float4 v = make_float4(0.f, 0.f, 0.f, 0.f);
            if (n < NP)
                v = *(const float4*)&inp[(size_t)(k0 + k) * NP + n];
            float4 d0 = {v.x, v.x, v.y, v.y};
            float4 d1 = {v.z, v.z, v.w, v.w};
            *(float4*)&Bs[k][n4 * 8]     = d0;
            *(float4*)&Bs[k][n4 * 8 + 4] = d1;
        }
        __syncthreads();
#pragma unroll
        for (int k = 0; k < 16; k++) {
            double2 bA = *(const double2*)&Bs[k][ty * 8];
            double2 bB = *(const double2*)&Bs[k][ty * 8 + 4];
            double2 kA = *(const double2*)&Ak[k][tx * 8];
            double2 kB = *(const double2*)&Ak[k][tx * 8 + 4];
            double2 vA = *(const double2*)&Av[k][tx * 8];
            double2 vB = *(const double2*)&Av[k][tx * 8 + 4];
            u64 bn[4]  = {d2u(bA.x), d2u(bA.y), d2u(bB.x), d2u(bB.y)};
            u64 akm[4] = {d2u(kA.x), d2u(kA.y), d2u(kB.x), d2u(kB.y)};
            u64 avm[4] = {d2u(vA.x), d2u(vA.y), d2u(vB.x), d2u(vB.y)};
#pragma unroll
            for (int i = 0; i < 4; i++)
#pragma unroll
                for (int j = 0; j < 4; j++) {
                    FMA_F32X2(ck[i][j], bn[i], akm[j], ck[i][j]);
                    FMA_F32X2(cv[i][j], bn[i], avm[j], cv[i][j]);
                }
        }
        __syncthreads();
    }
#pragma unroll
    for (int i = 0; i < 4; i++) {
        int n = n0 + ty * 4 + i;
        if (n >= NP) continue;
        size_t base = ((size_t)b * NP + n) * OUTC + o0 + tx * 8;
        float2 p0, p1, p2, p3;
        p0 = unpk(ck[i][0]); p1 = unpk(ck[i][1]);
        p2 = unpk(ck[i][2]); p3 = unpk(ck[i][3]);
        *(float4*)&g_k[base]     = make_float4(p0.x, p0.y, p1.x, p1.y);
        *(float4*)&g_k[base + 4] = make_float4(p2.x, p2.y, p3.x, p3.y);
        p0 = unpk(cv[i][0]); p1 = unpk(cv[i][1]);
        p2 = unpk(cv[i][2]); p3 = unpk(cv[i][3]);
        *(float4*)&g_v[base]     = make_float4(p0.x, p0.y, p1.x, p1.y);
        *(float4*)&g_v[base + 4] = make_float4(p2.x, p2.y, p3.x, p3.y);
    }
}

// ---------------------------------------------------------------------------
// 4) Attention: 128 threads/block, 2 threads per pixel (channel split).
//    Each half computes partial logits over its 16 channels; full logits are
//    reconstructed on both lanes via shfl.xor(1); softmax redundant; pass 2
//    is channel-split (no combine).  Doubles warps/SM at identical SMEM.
// ---------------------------------------------------------------------------
#define TPIX   14
#define NPIX   (TPIX*TPIX)              // 196
#define SSTR   197
#define ATTN_SMEM (2 * 8 * SSTR * 16 + CG * KK * 4)   // 51328 B

__global__ __launch_bounds__(128) void attn_kernel(const float* __restrict__ relh,
                                                   const float* __restrict__ relw,
                                                   float* __restrict__ out) {
    extern __shared__ float4 smbuf[];
    float4* ks   = smbuf;                       // [8][SSTR]
    float4* vs   = smbuf + 8 * SSTR;            // [8][SSTR]
    float*  bias = (float*)(smbuf + 16 * SSTR); // [32][7]

    const int b    = blockIdx.z;
    const int g    = blockIdx.y;
    const int tile = blockIdx.x;
    const int ty0  = (tile / 7) * 8;
    const int tx0  = (tile % 7) * 8;
    const int t    = threadIdx.x;
    const int p    = t >> 1;                    // pixel 0..63
    const int half = t & 1;                     // channel half

    const float* rel = (g < 4) ? (relh + (size_t)g * CG * KK)
                               : (relw + (size_t)(g - 4) * CG * KK);
    for (int i = t; i < CG * KK; i += 128) bias[i] = rel[i];

    for (int idx = t; idx < NPIX * 8; idx += 128) {
        int c4 = idx & 7;
        int pp = idx >> 3;
        int py = pp / TPIX, px = pp - py * TPIX;
        size_t gbase = (((size_t)b * HP + (ty0 + py)) * WP + (tx0 + px)) * OUTC + g * CG;
        ks[c4 * SSTR + pp] = *((const float4*)&g_k[gbase] + c4);
        vs[c4 * SSTR + pp] = *((const float4*)&g_v[gbase] + c4);
    }
    __syncthreads();

    const int lty = p >> 3, ltx = p & 7;
    const int h = ty0 + lty, w = tx0 + ltx;
    const int pbase = lty * TPIX + ltx;
    const int c4b = half * 4;                   // this lane's c4 range [c4b, c4b+4)

    // own 16 q channels
    float qf[16];
    {
        const float4* qp = (const float4*)&g_q[((size_t)b * NQ + h * WW + w) * OUTC + g * CG];
#pragma unroll
        for (int c4 = 0; c4 < 4; c4++) {
            float4 v = qp[c4b + c4];
            qf[c4 * 4 + 0] = v.x; qf[c4 * 4 + 1] = v.y;
            qf[c4 * 4 + 2] = v.z; qf[c4 * 4 + 3] = v.w;
        }
    }

    // partial bias dots over own channels
    float db[KK];
#pragma unroll
    for (int i = 0; i < KK; i++) {
        float s = 0.f;
#pragma unroll
        for (int c = 0; c < 16; c++) s += qf[c] * bias[(half * 16 + c) * KK + i];
        db[i] = s;
    }
#pragma unroll
    for (int i = 0; i < KK; i++) db[i] += __shfl_xor_sync(0xffffffffu, db[i], 1);

    // pass 1: partial logits over own channels, then combine across the pair
    float lg[KK * KK];
#pragma unroll
    for (int n = 0; n < KK * KK; n++) {
        const int i = n / KK, j = n % KK;
        const int pp = pbase + i * TPIX + j;
        float s = 0.f;
#pragma unroll
        for (int c4 = 0; c4 < 4; c4++) {
            float4 kv = ks[(c4b + c4) * SSTR + pp];
            s += qf[c4 * 4 + 0] * kv.x + qf[c4 * 4 + 1] * kv.y
               + qf[c4 * 4 + 2] * kv.z + qf[c4 * 4 + 3] * kv.w;
        }
        lg[n] = s;
    }
#pragma unroll
    for (int n = 0; n < KK * KK; n++)
        lg[n] += __shfl_xor_sync(0xffffffffu, lg[n], 1);
#pragma unroll
    for (int n = 0; n < KK * KK; n++)
        lg[n] += (g < 4) ? db[n / KK] : db[n % KK];

    // softmax (redundant on both lanes of the pair)
    float mx = lg[0];
#pragma unroll
    for (int n = 1; n < KK * KK; n++) mx = fmaxf(mx, lg[n]);
    float sum = 0.f;
#pragma unroll
    for (int n = 0; n < KK * KK; n++) { lg[n] = __expf(lg[n] - mx); sum += lg[n]; }
    float inv = 1.f / sum;
#pragma unroll
    for (int n = 0; n < KK * KK; n++) lg[n] *= inv;

    // pass 2: own channel half only
#pragma unroll
    for (int c4 = 0; c4 < 4; c4++) {
        float4 acc = make_float4(0.f, 0.f, 0.f, 0.f);
#pragma unroll
        for (int n = 0; n < KK * KK; n++) {
            const int pp = pbase + (n / KK) * TPIX + (n % KK);
            float4 vv = vs[(c4b + c4) * SSTR + pp];
            acc.x += lg[n] * vv.x;
            acc.y += lg[n] * vv.y;
            acc.z += lg[n] * vv.z;
            acc.w += lg[n] * vv.w;
        }
        size_t base = ((size_t)(b * OUTC + g * CG + (c4b + c4) * 4)) * NQ + h * WW + w;
        out[base]          = acc.x;
        out[base + NQ]     = acc.y;
        out[base + 2 * NQ] = acc.z;
        out[base + 3 * NQ] = acc.w;
    }
}

// ---------------------------------------------------------------------------
// Launch
// ---------------------------------------------------------------------------
extern "C" void kernel_launch(void* const* d_in, const int* in_sizes, int n_in,
                              void* d_out, int out_size) {
    const float* fm = (const float*)d_in[0];
    const float* wq = (const float*)d_in[1];
    const float* wk = (const float*)d_in[2];
    const float* wv = (const float*)d_in[3];
    const float* rh = (const float*)d_in[4];
    const float* rw = (const float*)d_in[5];
    float* out = (float*)d_out;

    cudaFuncSetAttribute(attn_kernel, cudaFuncAttributeMaxDynamicSharedMemorySize, ATTN_SMEM);

    {
        const int total = BB * CIN * NP;
        pad_kernel<<<(total + 255) / 256, 256>>>(fm);
    }
    gemm_q <<<dim3(NQ / 64, OUTC / 128, BB), 256>>>(fm, wq);
    gemm_kv<<<dim3((NP + 63) / 64, OUTC / 128, BB), 256>>>(wk, wv);
    attn_kernel<<<dim3(49, GRP, BB), 128, ATTN_SMEM>>>(rh, rw, out);
}

// round 4
// speedup vs baseline: 1.9319x; 1.9319x over previous
#include <cuda_runtime.h>
#include <cstdint>

// ---------------------------------------------------------------------------
// Problem constants
// ---------------------------------------------------------------------------
#define BB    2
#define CIN   256
#define HH    56
#define WW    56
#define OUTC  256
#define KK    7
#define PADV  3
#define GRP   8
#define CG    32
#define HP    62
#define WP    62
#define NQ    (HH*WW)     // 3136
#define NP    (HP*WP)     // 3844

#define KT    32          // k-tile
#define STR   36          // SMEM float stride for A/B tiles (conflict-free)
#define CSTR  132         // epilogue transpose stride

// ---------------------------------------------------------------------------
// MMA helpers (portable sm_80+ PTX — compiles for compute_103)
// ---------------------------------------------------------------------------
__device__ __forceinline__ void mma8(float* c, const uint32_t* a, const uint32_t* b) {
    asm volatile("mma.sync.aligned.m16n8k8.row.col.f32.tf32.tf32.f32 "
        "{%0,%1,%2,%3}, {%4,%5,%6,%7}, {%8,%9}, {%0,%1,%2,%3};"
        : "+f"(c[0]), "+f"(c[1]), "+f"(c[2]), "+f"(c[3])
        : "r"(a[0]), "r"(a[1]), "r"(a[2]), "r"(a[3]), "r"(b[0]), "r"(b[1]));
}
__device__ __forceinline__ uint32_t hi_bits(float x) {
    return __float_as_uint(x) & 0xFFFFE000u;    // top-10 mantissa bits: exact tf32
}
__device__ __forceinline__ uint32_t lo_tf32(float x, uint32_t h) {
    float lo = x - __uint_as_float(h);
    uint32_t r;
    asm("cvt.rna.tf32.f32 %0, %1;" : "=r"(r) : "f"(lo));
    return r;
}
__device__ __forceinline__ void split4(float4 v, uint4& h, uint4& l) {
    h.x = hi_bits(v.x); h.y = hi_bits(v.y); h.z = hi_bits(v.z); h.w = hi_bits(v.w);
    l.x = lo_tf32(v.x, h.x); l.y = lo_tf32(v.y, h.y);
    l.z = lo_tf32(v.z, h.z); l.w = lo_tf32(v.w, h.w);
}
// A fragment (m16 k8) at (mb, k0); r=lane>>2, q=lane&3
__device__ __forceinline__ void lda(uint32_t* f, const uint32_t* S, int mb, int k0, int r, int q) {
    f[0] = S[(mb + r)     * STR + k0 + q];
    f[1] = S[(mb + r + 8) * STR + k0 + q];
    f[2] = S[(mb + r)     * STR + k0 + q + 4];
    f[3] = S[(mb + r + 8) * STR + k0 + q + 4];
}
// B fragment (n8 k8) at (nb, k0)
__device__ __forceinline__ void ldb(uint32_t* f, const uint32_t* S, int nb, int k0, int r, int q) {
    f[0] = S[(nb + r) * STR + k0 + q];
    f[1] = S[(nb + r) * STR + k0 + q + 4];
}

// ---------------------------------------------------------------------------
// Scratch (device globals)
// ---------------------------------------------------------------------------
__device__ float g_pad[BB * CIN * NP];
__device__ float g_q  [BB * NQ  * OUTC];
__device__ float g_k  [BB * NP  * OUTC];
__device__ float g_v  [BB * NP  * OUTC];

// ---------------------------------------------------------------------------
// 1) Pad
// ---------------------------------------------------------------------------
__global__ void pad_kernel(const float* __restrict__ fm) {
    int idx = blockIdx.x * blockDim.x + threadIdx.x;
    const int total = BB * CIN * NP;
    if (idx >= total) return;
    int x = idx % WP;
    int t = idx / WP;
    int y = t % HP;  t /= HP;
    int c = t % CIN;
    int b = t / CIN;
    float v = 0.f;
    int hy = y - PADV, wx = x - PADV;
    if (hy >= 0 && hy < HH && wx >= 0 && wx < WW)
        v = fm[((size_t)(b * 2 * CIN + c) * HH + hy) * WW + wx];
    g_pad[idx] = v;
}

// ---------------------------------------------------------------------------
// 2) GEMM-Q via 3xTF32 mma.sync.  D[o(128)][n(128)], K=256.
//    SMEM floats: AH[128*36] AL BH BL.  Epilogue transpose via Ct[128][132].
// ---------------------------------------------------------------------------
#define Q_SMEMB (4 * 128 * STR * 4)          // 73728 B

__global__ __launch_bounds__(256) void gemm_q_mma(const float* __restrict__ fm,
                                                  const float* __restrict__ wq) {
    extern __shared__ uint32_t smu[];
    uint32_t* AH = smu;
    uint32_t* AL = smu + 128 * STR;
    uint32_t* BH = smu + 2 * 128 * STR;
    uint32_t* BL = smu + 3 * 128 * STR;

    const int t  = threadIdx.x;
    const int b  = blockIdx.z;
    const int o0 = blockIdx.y * 128;
    const int n0 = blockIdx.x * 128;
    const float* X = fm + (size_t)b * (2 * CIN) * NQ + (size_t)CIN * NQ;  // fm_t1

    const int wid = t >> 5, l = t & 31;
    const int wm = wid & 3, wn = wid >> 2;
    const int m0w = wm * 32, n0w = wn * 64;
    const int r = l >> 2, q = l & 3;

    float c[2][8][4];
#pragma unroll
    for (int mi = 0; mi < 2; mi++)
#pragma unroll
        for (int ni = 0; ni < 8; ni++)
#pragma unroll
            for (int e = 0; e < 4; e++) c[mi][ni][e] = 0.f;

    for (int kt = 0; kt < CIN / KT; kt++) {
        const int c0 = kt * KT;
        // gmem loads into regs first (overlap with prior compute tail)
        float4 av[4];
#pragma unroll
        for (int i = 0; i < 4; i++) {
            int id = t + i * 256;
            int m = id >> 3, f = id & 7;
            av[i] = *(const float4*)&wq[(size_t)(o0 + m) * CIN + c0 + f * 4];
        }
        float4 bv[4];
        {
            int cc = t & 31, grp = t >> 5;
#pragma unroll
            for (int j = 0; j < 4; j++) {
                int nb = n0 + grp * 16 + j * 4;
                bv[j] = (nb + 4 <= NQ) ? *(const float4*)&X[(size_t)(c0 + cc) * NQ + nb]
                                       : make_float4(0.f, 0.f, 0.f, 0.f);
            }
        }
        __syncthreads();
#pragma unroll
        for (int i = 0; i < 4; i++) {
            int id = t + i * 256;
            int m = id >> 3, f = id & 7;
            uint4 h, lo;
            split4(av[i], h, lo);
            *(uint4*)&AH[m * STR + f * 4] = h;
            *(uint4*)&AL[m * STR + f * 4] = lo;
        }
        {
            int cc = t & 31, grp = t >> 5;
#pragma unroll
            for (int j = 0; j < 4; j++) {
                uint4 h, lo;
                split4(bv[j], h, lo);
                int nb = grp * 16 + j * 4;
                BH[(nb + 0) * STR + cc] = h.x;  BL[(nb + 0) * STR + cc] = lo.x;
                BH[(nb + 1) * STR + cc] = h.y;  BL[(nb + 1) * STR + cc] = lo.y;
                BH[(nb + 2) * STR + cc] = h.z;  BL[(nb + 2) * STR + cc] = lo.z;
                BH[(nb + 3) * STR + cc] = h.w;  BL[(nb + 3) * STR + cc] = lo.w;
            }
        }
        __syncthreads();

#pragma unroll
        for (int ks = 0; ks < 4; ks++) {
            const int k0 = ks * 8;
            uint32_t ah[2][4], al[2][4];
            lda(ah[0], AH, m0w,      k0, r, q);
            lda(ah[1], AH, m0w + 16, k0, r, q);
            lda(al[0], AL, m0w,      k0, r, q);
            lda(al[1], AL, m0w + 16, k0, r, q);
#pragma unroll
            for (int ni = 0; ni < 8; ni++) {
                uint32_t bh[2], bl[2];
                ldb(bh, BH, n0w + ni * 8, k0, r, q);
                ldb(bl, BL, n0w + ni * 8, k0, r, q);
#pragma unroll
                for (int mi = 0; mi < 2; mi++) {
                    mma8(c[mi][ni], ah[mi], bh);
                    mma8(c[mi][ni], ah[mi], bl);
                    mma8(c[mi][ni], al[mi], bh);
                }
            }
        }
    }

    // Epilogue: transpose through SMEM -> coalesced channel-last stores
    __syncthreads();
    float* Ct = (float*)smu;                      // [128 n][CSTR]
#pragma unroll
    for (int mi = 0; mi < 2; mi++)
#pragma unroll
        for (int ni = 0; ni < 8; ni++) {
            int m = m0w + mi * 16 + r;
            int n = n0w + ni * 8 + q * 2;
            Ct[(n)     * CSTR + m]     = c[mi][ni][0];
            Ct[(n + 1) * CSTR + m]     = c[mi][ni][1];
            Ct[(n)     * CSTR + m + 8] = c[mi][ni][2];
            Ct[(n + 1) * CSTR + m + 8] = c[mi][ni][3];
        }
    __syncthreads();
#pragma unroll
    for (int i = 0; i < 16; i++) {
        int id = t + i * 256;
        int n = id >> 5, f = id & 31;
        if (n0 + n < NQ) {
            float4 v = *(float4*)&Ct[n * CSTR + f * 4];
            *(float4*)&g_q[((size_t)b * NQ + n0 + n) * OUTC + o0 + f * 4] = v;
        }
    }
}

// ---------------------------------------------------------------------------
// 3) Fused GEMM-KV via 3xTF32 mma.sync (shared B tile).
//    SMEM floats: KAH KAL VAH VAL BH BL (6 x 128*36).
// ---------------------------------------------------------------------------
#define KV_SMEMB (6 * 128 * STR * 4)         // 110592 B

__global__ __launch_bounds__(256) void gemm_kv_mma(const float* __restrict__ wk,
                                                   const float* __restrict__ wv) {
    extern __shared__ uint32_t smu[];
    uint32_t* KAH = smu;
    uint32_t* KAL = smu + 1 * 128 * STR;
    uint32_t* VAH = smu + 2 * 128 * STR;
    uint32_t* VAL = smu + 3 * 128 * STR;
    uint32_t* BH  = smu + 4 * 128 * STR;
    uint32_t* BL  = smu + 5 * 128 * STR;

    const int t  = threadIdx.x;
    const int b  = blockIdx.z;
    const int o0 = blockIdx.y * 128;
    const int n0 = blockIdx.x * 128;
    const float* X = g_pad + (size_t)b * CIN * NP;

    const int wid = t >> 5, l = t & 31;
    const int wm = wid & 3, wn = wid >> 2;
    const int m0w = wm * 32, n0w = wn * 64;
    const int r = l >> 2, q = l & 3;

    float ck[2][8][4], cv[2][8][4];
#pragma unroll
    for (int mi = 0; mi < 2; mi++)
#pragma unroll
        for (int ni = 0; ni < 8; ni++)
#pragma unroll
            for (int e = 0; e < 4; e++) { ck[mi][ni][e] = 0.f; cv[mi][ni][e] = 0.f; }

    for (int kt = 0; kt < CIN / KT; kt++) {
        const int c0 = kt * KT;
        float4 akv[4], avv[4];
#pragma unroll
        for (int i = 0; i < 4; i++) {
            int id = t + i * 256;
            int m = id >> 3, f = id & 7;
            akv[i] = *(const float4*)&wk[(size_t)(o0 + m) * CIN + c0 + f * 4];
            avv[i] = *(const float4*)&wv[(size_t)(o0 + m) * CIN + c0 + f * 4];
        }
        float4 bvv[4];
        {
            int cc = t & 31, grp = t >> 5;
#pragma unroll
            for (int j = 0; j < 4; j++) {
                int nb = n0 + grp * 16 + j * 4;
                bvv[j] = (nb + 4 <= NP) ? *(const float4*)&X[(size_t)(c0 + cc) * NP + nb]
                                        : make_float4(0.f, 0.f, 0.f, 0.f);
            }
        }
        __syncthreads();
#pragma unroll
        for (int i = 0; i < 4; i++) {
            int id = t + i * 256;
            int m = id >> 3, f = id & 7;
            uint4 h, lo;
            split4(akv[i], h, lo);
            *(uint4*)&KAH[m * STR + f * 4] = h;
            *(uint4*)&KAL[m * STR + f * 4] = lo;
            split4(avv[i], h, lo);
            *(uint4*)&VAH[m * STR + f * 4] = h;
            *(uint4*)&VAL[m * STR + f * 4] = lo;
        }
        {
            int cc = t & 31, grp = t >> 5;
#pragma unroll
            for (int j = 0; j < 4; j++) {
                uint4 h, lo;
                split4(bvv[j], h, lo);
                int nb = grp * 16 + j * 4;
                BH[(nb + 0) * STR + cc] = h.x;  BL[(nb + 0) * STR + cc] = lo.x;
                BH[(nb + 1) * STR + cc] = h.y;  BL[(nb + 1) * STR + cc] = lo.y;
                BH[(nb + 2) * STR + cc] = h.z;  BL[(nb + 2) * STR + cc] = lo.z;
                BH[(nb + 3) * STR + cc] = h.w;  BL[(nb + 3) * STR + cc] = lo.w;
            }
        }
        __syncthreads();

#pragma unroll
        for (int ks = 0; ks < 4; ks++) {
            const int k0 = ks * 8;
            uint32_t kh[2][4], kl[2][4], vh[2][4], vl[2][4];
            lda(kh[0], KAH, m0w,      k0, r, q);
            lda(kh[1], KAH, m0w + 16, k0, r, q);
            lda(kl[0], KAL, m0w,      k0, r, q);
            lda(kl[1], KAL, m0w + 16, k0, r, q);
            lda(vh[0], VAH, m0w,      k0, r, q);
            lda(vh[1], VAH, m0w + 16, k0, r, q);
            lda(vl[0], VAL, m0w,      k0, r, q);
            lda(vl[1], VAL, m0w + 16, k0, r, q);
#pragma unroll
            for (int ni = 0; ni < 8; ni++) {
                uint32_t bh[2], bl[2];
                ldb(bh, BH, n0w + ni * 8, k0, r, q);
                ldb(bl, BL, n0w + ni * 8, k0, r, q);
#pragma unroll
                for (int mi = 0; mi < 2; mi++) {
                    mma8(ck[mi][ni], kh[mi], bh);
                    mma8(ck[mi][ni], kh[mi], bl);
                    mma8(ck[mi][ni], kl[mi], bh);
                    mma8(cv[mi][ni], vh[mi], bh);
                    mma8(cv[mi][ni], vh[mi], bl);
                    mma8(cv[mi][ni], vl[mi], bh);
                }
            }
        }
    }

    // Epilogue: K then V through SMEM transpose
    float* Ct = (float*)smu;
#pragma unroll 1
    for (int pass = 0; pass < 2; pass++) {
        float (*C)[8][4] = pass ? cv : ck;
        float* dst = pass ? g_v : g_k;
        __syncthreads();
#pragma unroll
        for (int mi = 0; mi < 2; mi++)
#pragma unroll
            for (int ni = 0; ni < 8; ni++) {
                int m = m0w + mi * 16 + r;
                int n = n0w + ni * 8 + q * 2;
                Ct[(n)     * CSTR + m]     = C[mi][ni][0];
                Ct[(n + 1) * CSTR + m]     = C[mi][ni][1];
                Ct[(n)     * CSTR + m + 8] = C[mi][ni][2];
                Ct[(n + 1) * CSTR + m + 8] = C[mi][ni][3];
            }
        __syncthreads();
#pragma unroll
        for (int i = 0; i < 16; i++) {
            int id = t + i * 256;
            int n = id >> 5, f = id & 31;
            if (n0 + n < NP) {
                float4 v = *(float4*)&Ct[n * CSTR + f * 4];
                *(float4*)&dst[((size_t)b * NP + n0 + n) * OUTC + o0 + f * 4] = v;
            }
        }
    }
}

// ---------------------------------------------------------------------------
// 4) Attention (round-2 version: 128 thr/block, 2 threads per pixel)
// ---------------------------------------------------------------------------
#define TPIX   14
#define NPIX   (TPIX*TPIX)
#define SSTR   197
#define ATTN_SMEM (2 * 8 * SSTR * 16 + CG * KK * 4)   // 51328 B

__global__ __launch_bounds__(128) void attn_kernel(const float* __restrict__ relh,
                                                   const float* __restrict__ relw,
                                                   float* __restrict__ out) {
    extern __shared__ float4 smbuf[];
    float4* ks   = smbuf;
    float4* vs   = smbuf + 8 * SSTR;
    float*  bias = (float*)(smbuf + 16 * SSTR);

    const int b    = blockIdx.z;
    const int g    = blockIdx.y;
    const int tile = blockIdx.x;
    const int ty0  = (tile / 7) * 8;
    const int tx0  = (tile % 7) * 8;
    const int t    = threadIdx.x;
    const int p    = t >> 1;
    const int half = t & 1;

    const float* rel = (g < 4) ? (relh + (size_t)g * CG * KK)
                               : (relw + (size_t)(g - 4) * CG * KK);
    for (int i = t; i < CG * KK; i += 128) bias[i] = rel[i];

    for (int idx = t; idx < NPIX * 8; idx += 128) {
        int c4 = idx & 7;
        int pp = idx >> 3;
        int py = pp / TPIX, px = pp - py * TPIX;
        size_t gbase = (((size_t)b * HP + (ty0 + py)) * WP + (tx0 + px)) * OUTC + g * CG;
        ks[c4 * SSTR + pp] = *((const float4*)&g_k[gbase] + c4);
        vs[c4 * SSTR + pp] = *((const float4*)&g_v[gbase] + c4);
    }
    __syncthreads();

    const int lty = p >> 3, ltx = p & 7;
    const int h = ty0 + lty, w = tx0 + ltx;
    const int pbase = lty * TPIX + ltx;
    const int c4b = half * 4;

    float qf[16];
    {
        const float4* qp = (const float4*)&g_q[((size_t)b * NQ + h * WW + w) * OUTC + g * CG];
#pragma unroll
        for (int c4 = 0; c4 < 4; c4++) {
            float4 v = qp[c4b + c4];
            qf[c4 * 4 + 0] = v.x; qf[c4 * 4 + 1] = v.y;
            qf[c4 * 4 + 2] = v.z; qf[c4 * 4 + 3] = v.w;
        }
    }

    float db[KK];
#pragma unroll
    for (int i = 0; i < KK; i++) {
        float s = 0.f;
#pragma unroll
        for (int c = 0; c < 16; c++) s += qf[c] * bias[(half * 16 + c) * KK + i];
        db[i] = s;
    }
#pragma unroll
    for (int i = 0; i < KK; i++) db[i] += __shfl_xor_sync(0xffffffffu, db[i], 1);

    float lg[KK * KK];
#pragma unroll
    for (int n = 0; n < KK * KK; n++) {
        const int i = n / KK, j = n % KK;
        const int pp = pbase + i * TPIX + j;
        float s = 0.f;
#pragma unroll
        for (int c4 = 0; c4 < 4; c4++) {
            float4 kv = ks[(c4b + c4) * SSTR + pp];
            s += qf[c4 * 4 + 0] * kv.x + qf[c4 * 4 + 1] * kv.y
               + qf[c4 * 4 + 2] * kv.z + qf[c4 * 4 + 3] * kv.w;
        }
        lg[n] = s;
    }
#pragma unroll
    for (int n = 0; n < KK * KK; n++)
        lg[n] += __shfl_xor_sync(0xffffffffu, lg[n], 1);
#pragma unroll
    for (int n = 0; n < KK * KK; n++)
        lg[n] += (g < 4) ? db[n / KK] : db[n % KK];

    float mx = lg[0];
#pragma unroll
    for (int n = 1; n < KK * KK; n++) mx = fmaxf(mx, lg[n]);
    float sum = 0.f;
#pragma unroll
    for (int n = 0; n < KK * KK; n++) { lg[n] = __expf(lg[n] - mx); sum += lg[n]; }
    float inv = 1.f / sum;
#pragma unroll
    for (int n = 0; n < KK * KK; n++) lg[n] *= inv;

#pragma unroll
    for (int c4 = 0; c4 < 4; c4++) {
        float4 acc = make_float4(0.f, 0.f, 0.f, 0.f);
#pragma unroll
        for (int n = 0; n < KK * KK; n++) {
            const int pp = pbase + (n / KK) * TPIX + (n % KK);
            float4 vv = vs[(c4b + c4) * SSTR + pp];
            acc.x += lg[n] * vv.x;
            acc.y += lg[n] * vv.y;
            acc.z += lg[n] * vv.z;
            acc.w += lg[n] * vv.w;
        }
        size_t base = ((size_t)(b * OUTC + g * CG + (c4b + c4) * 4)) * NQ + h * WW + w;
        out[base]          = acc.x;
        out[base + NQ]     = acc.y;
        out[base + 2 * NQ] = acc.z;
        out[base + 3 * NQ] = acc.w;
    }
}

// ---------------------------------------------------------------------------
// Launch
// ---------------------------------------------------------------------------
extern "C" void kernel_launch(void* const* d_in, const int* in_sizes, int n_in,
                              void* d_out, int out_size) {
    const float* fm = (const float*)d_in[0];
    const float* wq = (const float*)d_in[1];
    const float* wk = (const float*)d_in[2];
    const float* wv = (const float*)d_in[3];
    const float* rh = (const float*)d_in[4];
    const float* rw = (const float*)d_in[5];
    float* out = (float*)d_out;

    cudaFuncSetAttribute(attn_kernel,  cudaFuncAttributeMaxDynamicSharedMemorySize, ATTN_SMEM);
    cudaFuncSetAttribute(gemm_q_mma,   cudaFuncAttributeMaxDynamicSharedMemorySize, Q_SMEMB);
    cudaFuncSetAttribute(gemm_kv_mma,  cudaFuncAttributeMaxDynamicSharedMemorySize, KV_SMEMB);

    {
        const int total = BB * CIN * NP;
        pad_kernel<<<(total + 255) / 256, 256>>>(fm);
    }
    gemm_q_mma <<<dim3((NQ + 127) / 128, OUTC / 128, BB), 256, Q_SMEMB>>>(fm, wq);
    gemm_kv_mma<<<dim3((NP + 127) / 128, OUTC / 128, BB), 256, KV_SMEMB>>>(wk, wv);
    attn_kernel<<<dim3(49, GRP, BB), 128, ATTN_SMEM>>>(rh, rw, out);
}

// round 5
// speedup vs baseline: 2.0670x; 1.0700x over previous
#include <cuda_runtime.h>
#include <cstdint>

// ---------------------------------------------------------------------------
// Problem constants
// ---------------------------------------------------------------------------
#define BB    2
#define CIN   256
#define HH    56
#define WW    56
#define OUTC  256
#define KK    7
#define PADV  3
#define GRP   8
#define CG    32
#define HP    62
#define WP    62
#define NQ    (HH*WW)     // 3136
#define NP    (HP*WP)     // 3844

#define KT    32          // k-tile
#define STR   36          // SMEM float stride (conflict-free frag reads)
#define CSTR  132         // epilogue transpose stride

// Q tiles: 49 n * 2 o * 2 b = 196 ; K/V tiles: 61 n * 2 o * 2 b = 244 each
#define QT    196
#define KTLS  244
#define TOT_TILES (QT + 2*KTLS)   // 684

// ---------------------------------------------------------------------------
// MMA helpers (portable sm_80+ PTX — compiles for compute_103)
// ---------------------------------------------------------------------------
__device__ __forceinline__ void mma8(float* c, const uint32_t* a, const uint32_t* b) {
    asm volatile("mma.sync.aligned.m16n8k8.row.col.f32.tf32.tf32.f32 "
        "{%0,%1,%2,%3}, {%4,%5,%6,%7}, {%8,%9}, {%0,%1,%2,%3};"
        : "+f"(c[0]), "+f"(c[1]), "+f"(c[2]), "+f"(c[3])
        : "r"(a[0]), "r"(a[1]), "r"(a[2]), "r"(a[3]), "r"(b[0]), "r"(b[1]));
}
__device__ __forceinline__ uint32_t hi_bits(float x) {
    return __float_as_uint(x) & 0xFFFFE000u;    // top-10 mantissa bits: exact tf32
}
__device__ __forceinline__ uint32_t lo_tf32(float x, uint32_t h) {
    float lo = x - __uint_as_float(h);
    uint32_t r;
    asm("cvt.rna.tf32.f32 %0, %1;" : "=r"(r) : "f"(lo));
    return r;
}
__device__ __forceinline__ void split4(float4 v, uint4& h, uint4& l) {
    h.x = hi_bits(v.x); h.y = hi_bits(v.y); h.z = hi_bits(v.z); h.w = hi_bits(v.w);
    l.x = lo_tf32(v.x, h.x); l.y = lo_tf32(v.y, h.y);
    l.z = lo_tf32(v.z, h.z); l.w = lo_tf32(v.w, h.w);
}
__device__ __forceinline__ void lda(uint32_t* f, const uint32_t* S, int mb, int k0, int r, int q) {
    f[0] = S[(mb + r)     * STR + k0 + q];
    f[1] = S[(mb + r + 8) * STR + k0 + q];
    f[2] = S[(mb + r)     * STR + k0 + q + 4];
    f[3] = S[(mb + r + 8) * STR + k0 + q + 4];
}
__device__ __forceinline__ void ldb(uint32_t* f, const uint32_t* S, int nb, int k0, int r, int q) {
    f[0] = S[(nb + r) * STR + k0 + q];
    f[1] = S[(nb + r) * STR + k0 + q + 4];
}

// ---------------------------------------------------------------------------
// Scratch (device globals)
// ---------------------------------------------------------------------------
__device__ float g_pad[BB * CIN * NP];
__device__ float g_q  [BB * NQ  * OUTC];
__device__ float g_k  [BB * NP  * OUTC];
__device__ float g_v  [BB * NP  * OUTC];

// ---------------------------------------------------------------------------
// 1) Pad
// ---------------------------------------------------------------------------
__global__ void pad_kernel(const float* __restrict__ fm) {
    int idx = blockIdx.x * blockDim.x + threadIdx.x;
    const int total = BB * CIN * NP;
    if (idx >= total) return;
    int x = idx % WP;
    int t = idx / WP;
    int y = t % HP;  t /= HP;
    int c = t % CIN;
    int b = t / CIN;
    float v = 0.f;
    int hy = y - PADV, wx = x - PADV;
    if (hy >= 0 && hy < HH && wx >= 0 && wx < WW)
        v = fm[((size_t)(b * 2 * CIN + c) * HH + hy) * WW + wx];
    g_pad[idx] = v;
}

// ---------------------------------------------------------------------------
// 2) Fused GEMM (Q / K / V block types) via 3xTF32 mma.sync
//    Tile: 128(o) x 64(n), K full 256.  8 warps in 4(m) x 2(n); warp 32x32.
//    SMEM: AH, AL [128*STR] ; BH, BL [64*STR]  = 55296 B  -> 2+ CTAs/SM.
// ---------------------------------------------------------------------------
#define G_SMEMB ((2*128 + 2*64) * STR * 4)     // 55296

__global__ __launch_bounds__(256, 2) void gemm_all(const float* __restrict__ fm,
                                                   const float* __restrict__ wq,
                                                   const float* __restrict__ wk,
                                                   const float* __restrict__ wv) {
    extern __shared__ uint32_t smu[];
    uint32_t* AH = smu;
    uint32_t* AL = smu + 128 * STR;
    uint32_t* BH = smu + 2 * 128 * STR;
    uint32_t* BL = smu + 2 * 128 * STR + 64 * STR;

    const int t = threadIdx.x;
    const int id = blockIdx.x;

    // decode block type + tile coords
    int local, nt;
    const float* W;
    if (id < QT)            { local = id;            nt = 49; W = wq; }
    else if (id < QT + KTLS){ local = id - QT;       nt = 61; W = wk; }
    else                    { local = id - QT - KTLS; nt = 61; W = wv; }
    const int ni_t = local % nt;
    const int rest = local / nt;          // b*2 + oi
    const int o0 = (rest & 1) * 128;
    const int b  = rest >> 1;
    const int n0 = ni_t * 64;

    const float* X;
    float* D;
    int NN;
    if (id < QT) {
        X = fm + (size_t)b * (2 * CIN) * NQ + (size_t)CIN * NQ;   // fm_t1
        D = g_q + (size_t)b * NQ * OUTC;
        NN = NQ;
    } else {
        X = g_pad + (size_t)b * CIN * NP;
        D = ((id < QT + KTLS) ? g_k : g_v) + (size_t)b * NP * OUTC;
        NN = NP;
    }

    const int wid = t >> 5, l = t & 31;
    const int m0w = (wid & 3) * 32;       // warp m origin
    const int n0w = (wid >> 2) * 32;      // warp n origin
    const int r = l >> 2, q = l & 3;

    float c[2][4][4];
#pragma unroll
    for (int mi = 0; mi < 2; mi++)
#pragma unroll
        for (int ni = 0; ni < 4; ni++)
#pragma unroll
            for (int e = 0; e < 4; e++) c[mi][ni][e] = 0.f;

    for (int kt = 0; kt < CIN / KT; kt++) {
        const int c0 = kt * KT;
        // stage gmem loads in regs (overlaps previous iteration's MMA tail)
        float4 av[4];
#pragma unroll
        for (int i = 0; i < 4; i++) {
            int id2 = t + i * 256;
            int m = id2 >> 3, f = id2 & 7;
            av[i] = *(const float4*)&W[(size_t)(o0 + m) * CIN + c0 + f * 4];
        }
        float4 bv[2];
        {
            int cc = t & 31, grp = t >> 5;     // [cc][grp*8 .. grp*8+7]
            int nb = n0 + grp * 8;
            bv[0] = (nb + 4 <= NN) ? *(const float4*)&X[(size_t)(c0 + cc) * NN + nb]
                                   : make_float4(0.f, 0.f, 0.f, 0.f);
            bv[1] = (nb + 8 <= NN) ? *(const float4*)&X[(size_t)(c0 + cc) * NN + nb + 4]
                                   : make_float4(0.f, 0.f, 0.f, 0.f);
        }
        __syncthreads();
#pragma unroll
        for (int i = 0; i < 4; i++) {
            int id2 = t + i * 256;
            int m = id2 >> 3, f = id2 & 7;
            uint4 h, lo;
            split4(av[i], h, lo);
            *(uint4*)&AH[m * STR + f * 4] = h;
            *(uint4*)&AL[m * STR + f * 4] = lo;
        }
        {
            int cc = t & 31, grp = t >> 5;
#pragma unroll
            for (int j = 0; j < 2; j++) {
                uint4 h, lo;
                split4(bv[j], h, lo);
                int nb = grp * 8 + j * 4;
                BH[(nb + 0) * STR + cc] = h.x;  BL[(nb + 0) * STR + cc] = lo.x;
                BH[(nb + 1) * STR + cc] = h.y;  BL[(nb + 1) * STR + cc] = lo.y;
                BH[(nb + 2) * STR + cc] = h.z;  BL[(nb + 2) * STR + cc] = lo.z;
                BH[(nb + 3) * STR + cc] = h.w;  BL[(nb + 3) * STR + cc] = lo.w;
            }
        }
        __syncthreads();

#pragma unroll
        for (int ks = 0; ks < 4; ks++) {
            const int k0 = ks * 8;
            uint32_t ah[2][4], al[2][4];
            lda(ah[0], AH, m0w,      k0, r, q);
            lda(ah[1], AH, m0w + 16, k0, r, q);
            lda(al[0], AL, m0w,      k0, r, q);
            lda(al[1], AL, m0w + 16, k0, r, q);
#pragma unroll
            for (int ni = 0; ni < 4; ni++) {
                uint32_t bh[2], bl[2];
                ldb(bh, BH, n0w + ni * 8, k0, r, q);
                ldb(bl, BL, n0w + ni * 8, k0, r, q);
#pragma unroll
                for (int mi = 0; mi < 2; mi++) {
                    mma8(c[mi][ni], ah[mi], bh);
                    mma8(c[mi][ni], ah[mi], bl);
                    mma8(c[mi][ni], al[mi], bh);
                }
            }
        }
    }

    // Epilogue: transpose through SMEM -> coalesced channel-last stores
    __syncthreads();
    float* Ct = (float*)smu;                 // [64 n][CSTR]
#pragma unroll
    for (int mi = 0; mi < 2; mi++)
#pragma unroll
        for (int ni = 0; ni < 4; ni++) {
            int m = m0w + mi * 16 + r;
            int n = n0w + ni * 8 + q * 2;
            Ct[(n)     * CSTR + m]     = c[mi][ni][0];
            Ct[(n + 1) * CSTR + m]     = c[mi][ni][1];
            Ct[(n)     * CSTR + m + 8] = c[mi][ni][2];
            Ct[(n + 1) * CSTR + m + 8] = c[mi][ni][3];
        }
    __syncthreads();
#pragma unroll
    for (int i = 0; i < 8; i++) {
        int id2 = t + i * 256;
        int n = id2 >> 5, f = id2 & 31;
        if (n0 + n < NN) {
            float4 v = *(float4*)&Ct[n * CSTR + f * 4];
            *(float4*)&D[(size_t)(n0 + n) * OUTC + o0 + f * 4] = v;
        }
    }
}

// ---------------------------------------------------------------------------
// 3) Attention (unchanged round-2 version)
// ---------------------------------------------------------------------------
#define TPIX   14
#define NPIX   (TPIX*TPIX)
#define SSTR   197
#define ATTN_SMEM (2 * 8 * SSTR * 16 + CG * KK * 4)   // 51328 B

__global__ __launch_bounds__(128) void attn_kernel(const float* __restrict__ relh,
                                                   const float* __restrict__ relw,
                                                   float* __restrict__ out) {
    extern __shared__ float4 smbuf[];
    float4* ks   = smbuf;
    float4* vs   = smbuf + 8 * SSTR;
    float*  bias = (float*)(smbuf + 16 * SSTR);

    const int b    = blockIdx.z;
    const int g    = blockIdx.y;
    const int tile = blockIdx.x;
    const int ty0  = (tile / 7) * 8;
    const int tx0  = (tile % 7) * 8;
    const int t    = threadIdx.x;
    const int p    = t >> 1;
    const int half = t & 1;

    const float* rel = (g < 4) ? (relh + (size_t)g * CG * KK)
                               : (relw + (size_t)(g - 4) * CG * KK);
    for (int i = t; i < CG * KK; i += 128) bias[i] = rel[i];

    for (int idx = t; idx < NPIX * 8; idx += 128) {
        int c4 = idx & 7;
        int pp = idx >> 3;
        int py = pp / TPIX, px = pp - py * TPIX;
        size_t gbase = (((size_t)b * HP + (ty0 + py)) * WP + (tx0 + px)) * OUTC + g * CG;
        ks[c4 * SSTR + pp] = *((const float4*)&g_k[gbase] + c4);
        vs[c4 * SSTR + pp] = *((const float4*)&g_v[gbase] + c4);
    }
    __syncthreads();

    const int lty = p >> 3, ltx = p & 7;
    const int h = ty0 + lty, w = tx0 + ltx;
    const int pbase = lty * TPIX + ltx;
    const int c4b = half * 4;

    float qf[16];
    {
        const float4* qp = (const float4*)&g_q[((size_t)b * NQ + h * WW + w) * OUTC + g * CG];
#pragma unroll
        for (int c4 = 0; c4 < 4; c4++) {
            float4 v = qp[c4b + c4];
            qf[c4 * 4 + 0] = v.x; qf[c4 * 4 + 1] = v.y;
            qf[c4 * 4 + 2] = v.z; qf[c4 * 4 + 3] = v.w;
        }
    }

    float db[KK];
#pragma unroll
    for (int i = 0; i < KK; i++) {
        float s = 0.f;
#pragma unroll
        for (int c = 0; c < 16; c++) s += qf[c] * bias[(half * 16 + c) * KK + i];
        db[i] = s;
    }
#pragma unroll
    for (int i = 0; i < KK; i++) db[i] += __shfl_xor_sync(0xffffffffu, db[i], 1);

    float lg[KK * KK];
#pragma unroll
    for (int n = 0; n < KK * KK; n++) {
        const int i = n / KK, j = n % KK;
        const int pp = pbase + i * TPIX + j;
        float s = 0.f;
#pragma unroll
        for (int c4 = 0; c4 < 4; c4++) {
            float4 kv = ks[(c4b + c4) * SSTR + pp];
            s += qf[c4 * 4 + 0] * kv.x + qf[c4 * 4 + 1] * kv.y
               + qf[c4 * 4 + 2] * kv.z + qf[c4 * 4 + 3] * kv.w;
        }
        lg[n] = s;
    }
#pragma unroll
    for (int n = 0; n < KK * KK; n++)
        lg[n] += __shfl_xor_sync(0xffffffffu, lg[n], 1);
#pragma unroll
    for (int n = 0; n < KK * KK; n++)
        lg[n] += (g < 4) ? db[n / KK] : db[n % KK];

    float mx = lg[0];
#pragma unroll
    for (int n = 1; n < KK * KK; n++) mx = fmaxf(mx, lg[n]);
    float sum = 0.f;
#pragma unroll
    for (int n = 0; n < KK * KK; n++) { lg[n] = __expf(lg[n] - mx); sum += lg[n]; }
    float inv = 1.f / sum;
#pragma unroll
    for (int n = 0; n < KK * KK; n++) lg[n] *= inv;

#pragma unroll
    for (int c4 = 0; c4 < 4; c4++) {
        float4 acc = make_float4(0.f, 0.f, 0.f, 0.f);
#pragma unroll
        for (int n = 0; n < KK * KK; n++) {
            const int pp = pbase + (n / KK) * TPIX + (n % KK);
            float4 vv = vs[(c4b + c4) * SSTR + pp];
            acc.x += lg[n] * vv.x;
            acc.y += lg[n] * vv.y;
            acc.z += lg[n] * vv.z;
            acc.w += lg[n] * vv.w;
        }
        size_t base = ((size_t)(b * OUTC + g * CG + (c4b + c4) * 4)) * NQ + h * WW + w;
        out[base]          = acc.x;
        out[base + NQ]     = acc.y;
        out[base + 2 * NQ] = acc.z;
        out[base + 3 * NQ] = acc.w;
    }
}

// ---------------------------------------------------------------------------
// Launch
// ---------------------------------------------------------------------------
extern "C" void kernel_launch(void* const* d_in, const int* in_sizes, int n_in,
                              void* d_out, int out_size) {
    const float* fm = (const float*)d_in[0];
    const float* wq = (const float*)d_in[1];
    const float* wk = (const float*)d_in[2];
    const float* wv = (const float*)d_in[3];
    const float* rh = (const float*)d_in[4];
    const float* rw = (const float*)d_in[5];
    float* out = (float*)d_out;

    cudaFuncSetAttribute(attn_kernel, cudaFuncAttributeMaxDynamicSharedMemorySize, ATTN_SMEM);
    cudaFuncSetAttribute(gemm_all,    cudaFuncAttributeMaxDynamicSharedMemorySize, G_SMEMB);

    {
        const int total = BB * CIN * NP;
        pad_kernel<<<(total + 255) / 256, 256>>>(fm);
    }
    gemm_all<<<TOT_TILES, 256, G_SMEMB>>>(fm, wq, wk, wv);
    attn_kernel<<<dim3(49, GRP, BB), 128, ATTN_SMEM>>>(rh, rw, out);
}